// round 10
// baseline (speedup 1.0000x reference)
#include <cuda_runtime.h>
#include <cuda_bf16.h>
#include <math.h>

#define BB 128
#define NN 256
#define EE 1024
#define DD 128
#define HH 8
#define DKK 16
#define DIN 130   // D + 2 degree features

// ---------------- scratch (device globals; no runtime allocation) ----------------
__device__ float g_deg_r[BB * NN];
__device__ float g_deg_c[BB * NN];
__device__ float g_q[BB * HH * NN * DKK];
__device__ float g_k[BB * HH * NN * DKK];
__device__ float g_v[BB * HH * NN * DKK];
__device__ float g_ef[BB * EE];
__device__ int   g_csr_ptr[BB * (NN + 1)];
__device__ int   g_csr_eid[BB * EE];
__device__ int   g_csr_col[BB * EE];
__device__ float g_wvec[DD];
__device__ float g_bmean;
__device__ float g_o[BB * NN * DD];
__device__ int   g_mask[BB * NN];
__device__ int   g_klist[BB * NN];
__device__ int   g_kcnt[BB];

// ---------------- packed f32x2 helpers (Blackwell FFMA2) ----------------
__device__ __forceinline__ unsigned long long fma2(unsigned long long a,
                                                   unsigned long long b,
                                                   unsigned long long c) {
    unsigned long long d;
    asm("fma.rn.f32x2 %0, %1, %2, %3;" : "=l"(d) : "l"(a), "l"(b), "l"(c));
    return d;
}
__device__ __forceinline__ unsigned long long pack2(float x, float y) {
    unsigned long long r;
    asm("mov.b64 %0, {%1, %2};" : "=l"(r) : "f"(x), "f"(y));
    return r;
}
__device__ __forceinline__ float2 unpack2(unsigned long long v) {
    float2 r;
    asm("mov.b64 {%0, %1}, %2;" : "=f"(r.x), "=f"(r.y) : "l"(v));
    return r;
}

// ---------------- kernel 1: mask normalize (+ block 0: wvec/bmean) ----------------
__global__ void k_mask_conv(const void* __restrict__ mp,
                            const float* __restrict__ Wew,
                            const float* __restrict__ Web) {
    const unsigned int* mw = reinterpret_cast<const unsigned int*>(mp);
    __shared__ int c_f32, c_big;
    if (threadIdx.x == 0) { c_f32 = 0; c_big = 0; }
    __syncthreads();
    int nf = 0, nb = 0;
    for (int i = threadIdx.x; i < 8192; i += 256) {
        unsigned int w = mw[i];
        if (w == 0x3F800000u) nf++;
        else if (w > 1u) nb++;
    }
    if (nf) atomicAdd(&c_f32, nf);
    if (nb) atomicAdd(&c_big, nb);
    __syncthreads();
    int f = (c_f32 > 64) ? 2 : (c_big > 64) ? 0 : 1;
    int i = blockIdx.x * 256 + threadIdx.x;
    int v;
    if (f == 2)      v = (reinterpret_cast<const float*>(mp)[i] != 0.0f);
    else if (f == 1) v = (reinterpret_cast<const int*>(mp)[i] != 0);
    else             v = (reinterpret_cast<const unsigned char*>(mp)[i] != 0);
    g_mask[i] = v;

    if (blockIdx.x == 0 && threadIdx.x < DD) {
        int r = threadIdx.x;
        float s = 0.f;
        for (int j = 0; j < DD; j++) s += Wew[r * DD + j];
        g_wvec[r] = s * (1.0f / DD);
        if (r == 0) {
            float b = 0.f;
            for (int j = 0; j < DD; j++) b += Web[j];
            g_bmean = b * (1.0f / DD);
        }
    }
}

// ---------------- kernel 2: degrees + CSR + compacted key list ----------------
__global__ void k_deg_csr(const int* __restrict__ ei) {
    int b = blockIdx.x, t = threadIdx.x;  // 256 threads
    __shared__ int hr[NN], hc[NN], sc[NN], off[NN];
    hr[t] = 0; hc[t] = 0;
    __syncthreads();
    const int* rows = ei + b * 2 * EE;
    const int* cols = rows + EE;
    for (int e = t; e < EE; e += 256) {
        atomicAdd(&hr[rows[e]], 1);
        atomicAdd(&hc[cols[e]], 1);
    }
    __syncthreads();
    g_deg_r[b * NN + t] = (float)hr[t];
    g_deg_c[b * NN + t] = (float)hc[t];
    sc[t] = hr[t];
    __syncthreads();
    for (int d = 1; d < NN; d <<= 1) {
        int v = (t >= d) ? sc[t - d] : 0;
        __syncthreads();
        sc[t] += v;
        __syncthreads();
    }
    if (t == 0) g_csr_ptr[b * (NN + 1)] = 0;
    g_csr_ptr[b * (NN + 1) + t + 1] = sc[t];
    off[t] = sc[t] - hr[t];
    __syncthreads();
    for (int e = t; e < EE; e += 256) {
        int r = rows[e];
        int pos = atomicAdd(&off[r], 1);
        g_csr_eid[b * EE + pos] = e;
        g_csr_col[b * EE + pos] = cols[e];
    }
    __syncthreads();
    int mv = g_mask[b * NN + t];
    sc[t] = mv;
    __syncthreads();
    for (int d = 1; d < NN; d <<= 1) {
        int v = (t >= d) ? sc[t - d] : 0;
        __syncthreads();
        sc[t] += v;
        __syncthreads();
    }
    if (mv) g_klist[b * NN + sc[t] - 1] = t;
    if (t == NN - 1) g_kcnt[b] = sc[t];
}

// ---------------- kernel 3: edge features (warp per edge) ----------------
__global__ void k_ef(const float* __restrict__ ea) {
    int warp = threadIdx.x >> 5, lane = threadIdx.x & 31;
    int e = blockIdx.x * 8 + warp;
    const float* row = ea + (size_t)e * DD;
    float4 a = *reinterpret_cast<const float4*>(row + lane * 4);
    float4 w = *reinterpret_cast<const float4*>(g_wvec + lane * 4);
    float d = a.x * w.x + a.y * w.y + a.z * w.z + a.w * w.w;
    #pragma unroll
    for (int o = 16; o; o >>= 1) d += __shfl_xor_sync(0xFFFFFFFFu, d, o);
    if (lane == 0) g_ef[e] = d + g_bmean;
}

// ---------------- kernel 4: QKV — 64-row tile, conflict-free W reads, 2 blocks/SM ----
// grid 512, block 256. Thread: 4 rows x 8 cols (cols tc*4..+3 and 64+tc*4..+3).
#define XT_STRIDE 68
__global__ void __launch_bounds__(256) k_qkv(const float* __restrict__ x,
                      const float* __restrict__ Wq,
                      const float* __restrict__ Wk,
                      const float* __restrict__ Wv) {
    extern __shared__ float smem[];
    float* xT  = smem;                       // [130][68] = 35,360 B
    float* W_s = smem + DIN * XT_STRIDE;     // [130][128] = 66,560 B
    int t = threadIdx.x;
    int r0g = blockIdx.x * 64;

    for (int i = t; i < 64 * DD; i += 256) {
        int row = i >> 7, k = i & 127;
        xT[k * XT_STRIDE + row] = x[(size_t)(r0g + row) * DD + k];
    }
    if (t < 64)       xT[128 * XT_STRIDE + t]        = g_deg_r[r0g + t];
    else if (t < 128) xT[129 * XT_STRIDE + (t - 64)] = g_deg_c[r0g + (t - 64)];

    int tr = t >> 4;           // 0..15 -> rows tr*4..tr*4+3
    int tc = t & 15;           // cols tc*4..+3 and 64+tc*4..+3 (conflict-free)
    int h1 = tc >> 2, dk1 = (tc & 3) * 4;

    for (int m = 0; m < 3; m++) {
        const float* W = (m == 0) ? Wq : (m == 1) ? Wk : Wv;
        float* out = (m == 0) ? g_q : (m == 1) ? g_k : g_v;
        __syncthreads();   // xT ready (m=0) / previous compute done (m>0)
        for (int i = t; i < DIN * DD / 4; i += 256)
            reinterpret_cast<float4*>(W_s)[i] = reinterpret_cast<const float4*>(W)[i];
        __syncthreads();

        unsigned long long acc[4][4];
        #pragma unroll
        for (int i = 0; i < 4; i++)
            #pragma unroll
            for (int j = 0; j < 4; j++) acc[i][j] = 0ull;

        #pragma unroll 2
        for (int k = 0; k < DIN; k++) {
            float4 a = *reinterpret_cast<const float4*>(xT + k * XT_STRIDE + tr * 4);
            const float* wr = W_s + k * DD + tc * 4;
            ulonglong2 b1 = *reinterpret_cast<const ulonglong2*>(wr);
            ulonglong2 b2 = *reinterpret_cast<const ulonglong2*>(wr + 64);
            unsigned long long a0 = pack2(a.x, a.x);
            unsigned long long a1 = pack2(a.y, a.y);
            unsigned long long a2 = pack2(a.z, a.z);
            unsigned long long a3 = pack2(a.w, a.w);
            acc[0][0] = fma2(a0, b1.x, acc[0][0]);
            acc[0][1] = fma2(a0, b1.y, acc[0][1]);
            acc[0][2] = fma2(a0, b2.x, acc[0][2]);
            acc[0][3] = fma2(a0, b2.y, acc[0][3]);
            acc[1][0] = fma2(a1, b1.x, acc[1][0]);
            acc[1][1] = fma2(a1, b1.y, acc[1][1]);
            acc[1][2] = fma2(a1, b2.x, acc[1][2]);
            acc[1][3] = fma2(a1, b2.y, acc[1][3]);
            acc[2][0] = fma2(a2, b1.x, acc[2][0]);
            acc[2][1] = fma2(a2, b1.y, acc[2][1]);
            acc[2][2] = fma2(a2, b2.x, acc[2][2]);
            acc[2][3] = fma2(a2, b2.y, acc[2][3]);
            acc[3][0] = fma2(a3, b1.x, acc[3][0]);
            acc[3][1] = fma2(a3, b1.y, acc[3][1]);
            acc[3][2] = fma2(a3, b2.x, acc[3][2]);
            acc[3][3] = fma2(a3, b2.y, acc[3][3]);
        }

        #pragma unroll
        for (int i = 0; i < 4; i++) {
            int row = r0g + tr * 4 + i;
            int bb = row >> 8, n = row & 255;
            float2 p0 = unpack2(acc[i][0]), p1 = unpack2(acc[i][1]);
            float2 p2 = unpack2(acc[i][2]), p3 = unpack2(acc[i][3]);
            *reinterpret_cast<float4*>(out + ((size_t)(bb * HH + h1) * NN + n) * DKK + dk1)
                = make_float4(p0.x, p0.y, p1.x, p1.y);
            *reinterpret_cast<float4*>(out + ((size_t)(bb * HH + 4 + h1) * NN + n) * DKK + dk1)
                = make_float4(p2.x, p2.y, p3.x, p3.y);
        }
    }
}

// ---------------- kernel 5: attention, pipelined, no-max softmax, 2 q/thread ----------------
// (measured 85.9 us in round 6 — reverted exactly)
__global__ void __launch_bounds__(128) k_attn() {
    int bh = blockIdx.x;           // b*H + h
    int b = bh >> 3, h = bh & 7;
    int t = threadIdx.x;           // 128 threads, queries t and t+128
    __shared__ __align__(16) float sk[NN * DKK];
    __shared__ __align__(16) float sv[NN * DKK];
    __shared__ int slist[NN];
    __shared__ int sm[NN];
    __shared__ int scnt;
    const float4* kg = reinterpret_cast<const float4*>(g_k + (size_t)bh * NN * DKK);
    const float4* vg = reinterpret_cast<const float4*>(g_v + (size_t)bh * NN * DKK);
    float4* sk4 = reinterpret_cast<float4*>(sk);
    float4* sv4 = reinterpret_cast<float4*>(sv);
    #pragma unroll
    for (int i = 0; i < 8; i++) {
        sk4[t + i * 128] = kg[t + i * 128];
        sv4[t + i * 128] = vg[t + i * 128];
    }
    sm[t] = g_mask[b * NN + t];
    sm[t + 128] = g_mask[b * NN + t + 128];
    slist[t] = g_klist[b * NN + t];
    slist[t + 128] = g_klist[b * NN + t + 128];
    if (t == 0) scnt = g_kcnt[b];
    __syncthreads();

    unsigned long long qA[8], qB[8];
    {
        const float4* qg = reinterpret_cast<const float4*>(g_q + ((size_t)bh * NN + t) * DKK);
        #pragma unroll
        for (int i = 0; i < 4; i++) {
            float4 qv = qg[i];
            qA[2 * i]     = pack2(qv.x, qv.y);
            qA[2 * i + 1] = pack2(qv.z, qv.w);
        }
        qg = reinterpret_cast<const float4*>(g_q + ((size_t)bh * NN + t + 128) * DKK);
        #pragma unroll
        for (int i = 0; i < 4; i++) {
            float4 qv = qg[i];
            qB[2 * i]     = pack2(qv.x, qv.y);
            qB[2 * i + 1] = pack2(qv.z, qv.w);
        }
    }

    float lA = 0.f, lB = 0.f;
    unsigned long long oA[8], oB[8];
    #pragma unroll
    for (int i = 0; i < 8; i++) { oA[i] = 0ull; oB[i] = 0ull; }

    int cnt = scnt;
    int jcur = slist[0];
    const ulonglong2* kp = reinterpret_cast<const ulonglong2*>(sk + jcur * DKK);
    ulonglong2 k0 = kp[0], k1 = kp[1], k2 = kp[2], k3 = kp[3];
    for (int jj = 0; jj < cnt; jj++) {
        int jv = jcur;
        int jn = slist[(jj + 1 < cnt) ? jj + 1 : jj];
        const ulonglong2* knp = reinterpret_cast<const ulonglong2*>(sk + jn * DKK);
        ulonglong2 nk0 = knp[0], nk1 = knp[1], nk2 = knp[2], nk3 = knp[3];

        unsigned long long aA = 0ull, aB = 0ull;
        aA = fma2(qA[0], k0.x, aA);  aB = fma2(qB[0], k0.x, aB);
        aA = fma2(qA[1], k0.y, aA);  aB = fma2(qB[1], k0.y, aB);
        aA = fma2(qA[2], k1.x, aA);  aB = fma2(qB[2], k1.x, aB);
        aA = fma2(qA[3], k1.y, aA);  aB = fma2(qB[3], k1.y, aB);
        aA = fma2(qA[4], k2.x, aA);  aB = fma2(qB[4], k2.x, aB);
        aA = fma2(qA[5], k2.y, aA);  aB = fma2(qB[5], k2.y, aB);
        aA = fma2(qA[6], k3.x, aA);  aB = fma2(qB[6], k3.x, aB);
        aA = fma2(qA[7], k3.y, aA);  aB = fma2(qB[7], k3.y, aB);
        float2 hA = unpack2(aA), hB = unpack2(aB);
        float pA = __expf((hA.x + hA.y) * 0.25f);
        float pB = __expf((hB.x + hB.y) * 0.25f);
        lA += pA;  lB += pB;
        unsigned long long p2A = pack2(pA, pA);
        unsigned long long p2B = pack2(pB, pB);
        const ulonglong2* vp = reinterpret_cast<const ulonglong2*>(sv + jv * DKK);
        ulonglong2 v0 = vp[0], v1 = vp[1], v2 = vp[2], v3 = vp[3];
        oA[0] = fma2(p2A, v0.x, oA[0]);  oB[0] = fma2(p2B, v0.x, oB[0]);
        oA[1] = fma2(p2A, v0.y, oA[1]);  oB[1] = fma2(p2B, v0.y, oB[1]);
        oA[2] = fma2(p2A, v1.x, oA[2]);  oB[2] = fma2(p2B, v1.x, oB[2]);
        oA[3] = fma2(p2A, v1.y, oA[3]);  oB[3] = fma2(p2B, v1.y, oB[3]);
        oA[4] = fma2(p2A, v2.x, oA[4]);  oB[4] = fma2(p2B, v2.x, oB[4]);
        oA[5] = fma2(p2A, v2.y, oA[5]);  oB[5] = fma2(p2B, v2.y, oB[5]);
        oA[6] = fma2(p2A, v3.x, oA[6]);  oB[6] = fma2(p2B, v3.x, oB[6]);
        oA[7] = fma2(p2A, v3.y, oA[7]);  oB[7] = fma2(p2B, v3.y, oB[7]);
        jcur = jn;
        k0 = nk0; k1 = nk1; k2 = nk2; k3 = nk3;
    }

    // sparse edge-bias correction: exp(s+f) = exp(s) + exp(s)*expm1(f)
    int base = b * EE;
    #pragma unroll
    for (int qi = 0; qi < 2; qi++) {
        int q = t + qi * 128;
        const unsigned long long* qq = qi ? qB : qA;
        unsigned long long* oo = qi ? oB : oA;
        float* ll = qi ? &lB : &lA;
        int p0 = g_csr_ptr[b * (NN + 1) + q];
        int p1 = g_csr_ptr[b * (NN + 1) + q + 1];
        for (int idx = p0; idx < p1; idx++) {
            int c = g_csr_col[base + idx];
            if (!sm[c]) continue;
            float f = g_ef[base + g_csr_eid[base + idx]];
            const ulonglong2* kpp = reinterpret_cast<const ulonglong2*>(sk + c * DKK);
            ulonglong2 c0v = kpp[0], c1v = kpp[1], c2v = kpp[2], c3v = kpp[3];
            unsigned long long a = 0ull;
            a = fma2(qq[0], c0v.x, a);
            a = fma2(qq[1], c0v.y, a);
            a = fma2(qq[2], c1v.x, a);
            a = fma2(qq[3], c1v.y, a);
            a = fma2(qq[4], c2v.x, a);
            a = fma2(qq[5], c2v.y, a);
            a = fma2(qq[6], c3v.x, a);
            a = fma2(qq[7], c3v.y, a);
            float2 hh = unpack2(a);
            float w = __expf((hh.x + hh.y) * 0.25f) * expm1f(f);
            *ll += w;
            unsigned long long w2 = pack2(w, w);
            const ulonglong2* vp = reinterpret_cast<const ulonglong2*>(sv + c * DKK);
            ulonglong2 v0 = vp[0], v1 = vp[1], v2 = vp[2], v3 = vp[3];
            oo[0] = fma2(w2, v0.x, oo[0]);
            oo[1] = fma2(w2, v0.y, oo[1]);
            oo[2] = fma2(w2, v1.x, oo[2]);
            oo[3] = fma2(w2, v1.y, oo[3]);
            oo[4] = fma2(w2, v2.x, oo[4]);
            oo[5] = fma2(w2, v2.y, oo[5]);
            oo[6] = fma2(w2, v3.x, oo[6]);
            oo[7] = fma2(w2, v3.y, oo[7]);
        }
    }

    float invA = 1.0f / lA, invB = 1.0f / lB;
    float* og = g_o + ((size_t)(b * NN + t)) * DD + h * DKK;
    #pragma unroll
    for (int i = 0; i < 4; i++) {
        float2 e0 = unpack2(oA[2 * i]);
        float2 e1 = unpack2(oA[2 * i + 1]);
        reinterpret_cast<float4*>(og)[i] =
            make_float4(e0.x * invA, e0.y * invA, e1.x * invA, e1.y * invA);
    }
    og = g_o + ((size_t)(b * NN + t + 128)) * DD + h * DKK;
    #pragma unroll
    for (int i = 0; i < 4; i++) {
        float2 e0 = unpack2(oB[2 * i]);
        float2 e1 = unpack2(oB[2 * i + 1]);
        reinterpret_cast<float4*>(og)[i] =
            make_float4(e0.x * invB, e0.y * invB, e1.x * invB, e1.y * invB);
    }
}

// ---------------- kernel 6: residual + layernorm ----------------
__global__ void k_ln(const float* __restrict__ x,
                     const float* __restrict__ lg,
                     const float* __restrict__ lb,
                     float* __restrict__ out) {
    int warp = threadIdx.x >> 5, lane = threadIdx.x & 31;
    int row = blockIdx.x * 8 + warp;
    int c0 = lane * 4;
    float4 o = *reinterpret_cast<const float4*>(g_o + (size_t)row * DD + c0);
    float4 xv = *reinterpret_cast<const float4*>(x + (size_t)row * DD + c0);
    float4 s = make_float4(o.x + xv.x, o.y + xv.y, o.z + xv.z, o.w + xv.w);
    float sum = s.x + s.y + s.z + s.w;
    float sq  = s.x * s.x + s.y * s.y + s.z * s.z + s.w * s.w;
    #pragma unroll
    for (int off = 16; off; off >>= 1) {
        sum += __shfl_xor_sync(0xFFFFFFFFu, sum, off);
        sq  += __shfl_xor_sync(0xFFFFFFFFu, sq, off);
    }
    float mu = sum * (1.0f / DD);
    float var = sq * (1.0f / DD) - mu * mu;
    float rstd = rsqrtf(var + 1e-6f);
    float4 g = *reinterpret_cast<const float4*>(lg + c0);
    float4 be = *reinterpret_cast<const float4*>(lb + c0);
    float4 r;
    r.x = (s.x - mu) * rstd * g.x + be.x;
    r.y = (s.y - mu) * rstd * g.y + be.y;
    r.z = (s.z - mu) * rstd * g.z + be.z;
    r.w = (s.w - mu) * rstd * g.w + be.w;
    *reinterpret_cast<float4*>(out + (size_t)row * DD + c0) = r;
}

// ---------------- launch ----------------
extern "C" void kernel_launch(void* const* d_in, const int* in_sizes, int n_in,
                              void* d_out, int out_size) {
    const float* x    = (const float*)d_in[0];
    const void*  mask = d_in[1];
    const int*   ei   = (const int*)d_in[2];
    const float* ea   = (const float*)d_in[3];
    const float* Wq   = (const float*)d_in[4];
    const float* Wk   = (const float*)d_in[5];
    const float* Wv   = (const float*)d_in[6];
    const float* Wew  = (const float*)d_in[7];
    const float* Web  = (const float*)d_in[8];
    const float* lg   = (const float*)d_in[9];
    const float* lb   = (const float*)d_in[10];
    float* out = (float*)d_out;

    // qkv is launch #4 — the ncu-captured slot.
    k_mask_conv<<<(BB * NN) / 256, 256>>>(mask, Wew, Web);
    k_deg_csr<<<BB, 256>>>(ei);
    k_ef<<<(BB * EE) / 8, 256>>>(ea);

    int smem_qkv = (DIN * XT_STRIDE + DIN * DD) * (int)sizeof(float);
    cudaFuncSetAttribute(k_qkv, cudaFuncAttributeMaxDynamicSharedMemorySize, smem_qkv);
    k_qkv<<<(BB * NN) / 64, 256, smem_qkv>>>(x, Wq, Wk, Wv);

    k_attn<<<BB * HH, 128>>>();
    k_ln<<<(BB * NN) / 8, 256>>>(x, lg, lb, out);
}

// round 11
// speedup vs baseline: 1.0135x; 1.0135x over previous
#include <cuda_runtime.h>
#include <cuda_bf16.h>
#include <math.h>

#define BB 128
#define NN 256
#define EE 1024
#define DD 128
#define HH 8
#define DKK 16
#define DIN 130   // D + 2 degree features

// ---------------- scratch (device globals; no runtime allocation) ----------------
__device__ float g_deg_r[BB * NN];
__device__ float g_deg_c[BB * NN];
__device__ float g_q[BB * HH * NN * DKK];
__device__ float g_k[BB * HH * NN * DKK];
__device__ float g_v[BB * HH * NN * DKK];
__device__ float g_ef[BB * EE];
__device__ int   g_csr_ptr[BB * (NN + 1)];
__device__ int   g_csr_eid[BB * EE];
__device__ int   g_csr_col[BB * EE];
__device__ float g_wvec[DD];
__device__ float g_bmean;
__device__ float g_o[BB * NN * DD];
__device__ int   g_mask[BB * NN];
__device__ int   g_klist[BB * NN];
__device__ int   g_kcnt[BB];

// ---------------- packed f32x2 helpers (Blackwell FFMA2) ----------------
__device__ __forceinline__ unsigned long long fma2(unsigned long long a,
                                                   unsigned long long b,
                                                   unsigned long long c) {
    unsigned long long d;
    asm("fma.rn.f32x2 %0, %1, %2, %3;" : "=l"(d) : "l"(a), "l"(b), "l"(c));
    return d;
}
__device__ __forceinline__ unsigned long long pack2(float x, float y) {
    unsigned long long r;
    asm("mov.b64 %0, {%1, %2};" : "=l"(r) : "f"(x), "f"(y));
    return r;
}
__device__ __forceinline__ float2 unpack2(unsigned long long v) {
    float2 r;
    asm("mov.b64 {%0, %1}, %2;" : "=f"(r.x), "=f"(r.y) : "l"(v));
    return r;
}

// ---------------- kernel 1: mask normalize (+ block 0: wvec/bmean) ----------------
__global__ void k_mask_conv(const void* __restrict__ mp,
                            const float* __restrict__ Wew,
                            const float* __restrict__ Web) {
    const unsigned int* mw = reinterpret_cast<const unsigned int*>(mp);
    __shared__ int c_f32, c_big;
    if (threadIdx.x == 0) { c_f32 = 0; c_big = 0; }
    __syncthreads();
    int nf = 0, nb = 0;
    for (int i = threadIdx.x; i < 8192; i += 256) {
        unsigned int w = mw[i];
        if (w == 0x3F800000u) nf++;
        else if (w > 1u) nb++;
    }
    if (nf) atomicAdd(&c_f32, nf);
    if (nb) atomicAdd(&c_big, nb);
    __syncthreads();
    int f = (c_f32 > 64) ? 2 : (c_big > 64) ? 0 : 1;
    int i = blockIdx.x * 256 + threadIdx.x;
    int v;
    if (f == 2)      v = (reinterpret_cast<const float*>(mp)[i] != 0.0f);
    else if (f == 1) v = (reinterpret_cast<const int*>(mp)[i] != 0);
    else             v = (reinterpret_cast<const unsigned char*>(mp)[i] != 0);
    g_mask[i] = v;

    if (blockIdx.x == 0 && threadIdx.x < DD) {
        int r = threadIdx.x;
        float s = 0.f;
        for (int j = 0; j < DD; j++) s += Wew[r * DD + j];
        g_wvec[r] = s * (1.0f / DD);
        if (r == 0) {
            float b = 0.f;
            for (int j = 0; j < DD; j++) b += Web[j];
            g_bmean = b * (1.0f / DD);
        }
    }
}

// ---------------- kernel 2: degrees + CSR + compacted key list ----------------
__global__ void k_deg_csr(const int* __restrict__ ei) {
    int b = blockIdx.x, t = threadIdx.x;  // 256 threads
    __shared__ int hr[NN], hc[NN], sc[NN], off[NN];
    hr[t] = 0; hc[t] = 0;
    __syncthreads();
    const int* rows = ei + b * 2 * EE;
    const int* cols = rows + EE;
    for (int e = t; e < EE; e += 256) {
        atomicAdd(&hr[rows[e]], 1);
        atomicAdd(&hc[cols[e]], 1);
    }
    __syncthreads();
    g_deg_r[b * NN + t] = (float)hr[t];
    g_deg_c[b * NN + t] = (float)hc[t];
    sc[t] = hr[t];
    __syncthreads();
    for (int d = 1; d < NN; d <<= 1) {
        int v = (t >= d) ? sc[t - d] : 0;
        __syncthreads();
        sc[t] += v;
        __syncthreads();
    }
    if (t == 0) g_csr_ptr[b * (NN + 1)] = 0;
    g_csr_ptr[b * (NN + 1) + t + 1] = sc[t];
    off[t] = sc[t] - hr[t];
    __syncthreads();
    for (int e = t; e < EE; e += 256) {
        int r = rows[e];
        int pos = atomicAdd(&off[r], 1);
        g_csr_eid[b * EE + pos] = e;
        g_csr_col[b * EE + pos] = cols[e];
    }
    __syncthreads();
    int mv = g_mask[b * NN + t];
    sc[t] = mv;
    __syncthreads();
    for (int d = 1; d < NN; d <<= 1) {
        int v = (t >= d) ? sc[t - d] : 0;
        __syncthreads();
        sc[t] += v;
        __syncthreads();
    }
    if (mv) g_klist[b * NN + sc[t] - 1] = t;
    if (t == NN - 1) g_kcnt[b] = sc[t];
}

// ---------------- kernel 3: edge features (warp per edge) ----------------
__global__ void k_ef(const float* __restrict__ ea) {
    int warp = threadIdx.x >> 5, lane = threadIdx.x & 31;
    int e = blockIdx.x * 8 + warp;
    const float* row = ea + (size_t)e * DD;
    float4 a = *reinterpret_cast<const float4*>(row + lane * 4);
    float4 w = *reinterpret_cast<const float4*>(g_wvec + lane * 4);
    float d = a.x * w.x + a.y * w.y + a.z * w.z + a.w * w.w;
    #pragma unroll
    for (int o = 16; o; o >>= 1) d += __shfl_xor_sync(0xFFFFFFFFu, d, o);
    if (lane == 0) g_ef[e] = d + g_bmean;
}

// ---------------- kernel 4: QKV — 64-row tile, 8x8 thread tile, 128 threads ----------
// grid 512, block 128. Thread: 8 rows (tr*8..+7) x 8 cols (tc*4..+3, 64+tc*4..+3).
#define XT_STRIDE 68
__global__ void __launch_bounds__(128) k_qkv(const float* __restrict__ x,
                      const float* __restrict__ Wq,
                      const float* __restrict__ Wk,
                      const float* __restrict__ Wv) {
    extern __shared__ float smem[];
    float* xT  = smem;                       // [130][68] = 35,360 B
    float* W_s = smem + DIN * XT_STRIDE;     // [130][128] = 66,560 B
    int t = threadIdx.x;
    int r0g = blockIdx.x * 64;

    // stage xT (transposed x tile): coalesced LDG.32
    for (int i = t; i < 64 * DD; i += 128) {
        int row = i >> 7, k = i & 127;
        xT[k * XT_STRIDE + row] = x[(size_t)(r0g + row) * DD + k];
    }
    if (t < 64)       xT[128 * XT_STRIDE + t]        = g_deg_r[r0g + t];
    else if (t < 128) xT[129 * XT_STRIDE + (t - 64)] = g_deg_c[r0g + (t - 64)];

    int tr = t >> 4;           // 0..7 -> rows tr*8..tr*8+7
    int tc = t & 15;           // cols tc*4..+3 and 64+tc*4..+3 (conflict-free)
    int h1 = tc >> 2, dk1 = (tc & 3) * 4;

    for (int m = 0; m < 3; m++) {
        const float* W = (m == 0) ? Wq : (m == 1) ? Wk : Wv;
        float* out = (m == 0) ? g_q : (m == 1) ? g_k : g_v;
        __syncthreads();   // xT ready (m=0) / previous compute done (m>0)
        for (int i = t; i < DIN * DD / 4; i += 128)
            reinterpret_cast<float4*>(W_s)[i] = reinterpret_cast<const float4*>(W)[i];
        __syncthreads();

        unsigned long long acc[8][4];
        #pragma unroll
        for (int i = 0; i < 8; i++)
            #pragma unroll
            for (int j = 0; j < 4; j++) acc[i][j] = 0ull;

        #pragma unroll 2
        for (int k = 0; k < DIN; k++) {
            const float* ar = xT + k * XT_STRIDE + tr * 8;
            float4 aL = *reinterpret_cast<const float4*>(ar);
            float4 aH = *reinterpret_cast<const float4*>(ar + 4);
            const float* wr = W_s + k * DD + tc * 4;
            ulonglong2 b1 = *reinterpret_cast<const ulonglong2*>(wr);
            ulonglong2 b2 = *reinterpret_cast<const ulonglong2*>(wr + 64);
            float av[8] = {aL.x, aL.y, aL.z, aL.w, aH.x, aH.y, aH.z, aH.w};
            #pragma unroll
            for (int i = 0; i < 8; i++) {
                unsigned long long a2 = pack2(av[i], av[i]);
                acc[i][0] = fma2(a2, b1.x, acc[i][0]);
                acc[i][1] = fma2(a2, b1.y, acc[i][1]);
                acc[i][2] = fma2(a2, b2.x, acc[i][2]);
                acc[i][3] = fma2(a2, b2.y, acc[i][3]);
            }
        }

        #pragma unroll
        for (int i = 0; i < 8; i++) {
            int row = r0g + tr * 8 + i;
            int bb = row >> 8, n = row & 255;
            float2 p0 = unpack2(acc[i][0]), p1 = unpack2(acc[i][1]);
            float2 p2 = unpack2(acc[i][2]), p3 = unpack2(acc[i][3]);
            *reinterpret_cast<float4*>(out + ((size_t)(bb * HH + h1) * NN + n) * DKK + dk1)
                = make_float4(p0.x, p0.y, p1.x, p1.y);
            *reinterpret_cast<float4*>(out + ((size_t)(bb * HH + 4 + h1) * NN + n) * DKK + dk1)
                = make_float4(p2.x, p2.y, p3.x, p3.y);
        }
    }
}

// ---------------- kernel 5: attention, pipelined, no-max softmax, 2 q/thread ----------------
// (measured 85.9 us — unchanged)
__global__ void __launch_bounds__(128) k_attn() {
    int bh = blockIdx.x;           // b*H + h
    int b = bh >> 3, h = bh & 7;
    int t = threadIdx.x;           // 128 threads, queries t and t+128
    __shared__ __align__(16) float sk[NN * DKK];
    __shared__ __align__(16) float sv[NN * DKK];
    __shared__ int slist[NN];
    __shared__ int sm[NN];
    __shared__ int scnt;
    const float4* kg = reinterpret_cast<const float4*>(g_k + (size_t)bh * NN * DKK);
    const float4* vg = reinterpret_cast<const float4*>(g_v + (size_t)bh * NN * DKK);
    float4* sk4 = reinterpret_cast<float4*>(sk);
    float4* sv4 = reinterpret_cast<float4*>(sv);
    #pragma unroll
    for (int i = 0; i < 8; i++) {
        sk4[t + i * 128] = kg[t + i * 128];
        sv4[t + i * 128] = vg[t + i * 128];
    }
    sm[t] = g_mask[b * NN + t];
    sm[t + 128] = g_mask[b * NN + t + 128];
    slist[t] = g_klist[b * NN + t];
    slist[t + 128] = g_klist[b * NN + t + 128];
    if (t == 0) scnt = g_kcnt[b];
    __syncthreads();

    unsigned long long qA[8], qB[8];
    {
        const float4* qg = reinterpret_cast<const float4*>(g_q + ((size_t)bh * NN + t) * DKK);
        #pragma unroll
        for (int i = 0; i < 4; i++) {
            float4 qv = qg[i];
            qA[2 * i]     = pack2(qv.x, qv.y);
            qA[2 * i + 1] = pack2(qv.z, qv.w);
        }
        qg = reinterpret_cast<const float4*>(g_q + ((size_t)bh * NN + t + 128) * DKK);
        #pragma unroll
        for (int i = 0; i < 4; i++) {
            float4 qv = qg[i];
            qB[2 * i]     = pack2(qv.x, qv.y);
            qB[2 * i + 1] = pack2(qv.z, qv.w);
        }
    }

    float lA = 0.f, lB = 0.f;
    unsigned long long oA[8], oB[8];
    #pragma unroll
    for (int i = 0; i < 8; i++) { oA[i] = 0ull; oB[i] = 0ull; }

    int cnt = scnt;
    int jcur = slist[0];
    const ulonglong2* kp = reinterpret_cast<const ulonglong2*>(sk + jcur * DKK);
    ulonglong2 k0 = kp[0], k1 = kp[1], k2 = kp[2], k3 = kp[3];
    for (int jj = 0; jj < cnt; jj++) {
        int jv = jcur;
        int jn = slist[(jj + 1 < cnt) ? jj + 1 : jj];
        const ulonglong2* knp = reinterpret_cast<const ulonglong2*>(sk + jn * DKK);
        ulonglong2 nk0 = knp[0], nk1 = knp[1], nk2 = knp[2], nk3 = knp[3];

        unsigned long long aA = 0ull, aB = 0ull;
        aA = fma2(qA[0], k0.x, aA);  aB = fma2(qB[0], k0.x, aB);
        aA = fma2(qA[1], k0.y, aA);  aB = fma2(qB[1], k0.y, aB);
        aA = fma2(qA[2], k1.x, aA);  aB = fma2(qB[2], k1.x, aB);
        aA = fma2(qA[3], k1.y, aA);  aB = fma2(qB[3], k1.y, aB);
        aA = fma2(qA[4], k2.x, aA);  aB = fma2(qB[4], k2.x, aB);
        aA = fma2(qA[5], k2.y, aA);  aB = fma2(qB[5], k2.y, aB);
        aA = fma2(qA[6], k3.x, aA);  aB = fma2(qB[6], k3.x, aB);
        aA = fma2(qA[7], k3.y, aA);  aB = fma2(qB[7], k3.y, aB);
        float2 hA = unpack2(aA), hB = unpack2(aB);
        float pA = __expf((hA.x + hA.y) * 0.25f);
        float pB = __expf((hB.x + hB.y) * 0.25f);
        lA += pA;  lB += pB;
        unsigned long long p2A = pack2(pA, pA);
        unsigned long long p2B = pack2(pB, pB);
        const ulonglong2* vp = reinterpret_cast<const ulonglong2*>(sv + jv * DKK);
        ulonglong2 v0 = vp[0], v1 = vp[1], v2 = vp[2], v3 = vp[3];
        oA[0] = fma2(p2A, v0.x, oA[0]);  oB[0] = fma2(p2B, v0.x, oB[0]);
        oA[1] = fma2(p2A, v0.y, oA[1]);  oB[1] = fma2(p2B, v0.y, oB[1]);
        oA[2] = fma2(p2A, v1.x, oA[2]);  oB[2] = fma2(p2B, v1.x, oB[2]);
        oA[3] = fma2(p2A, v1.y, oA[3]);  oB[3] = fma2(p2B, v1.y, oB[3]);
        oA[4] = fma2(p2A, v2.x, oA[4]);  oB[4] = fma2(p2B, v2.x, oB[4]);
        oA[5] = fma2(p2A, v2.y, oA[5]);  oB[5] = fma2(p2B, v2.y, oB[5]);
        oA[6] = fma2(p2A, v3.x, oA[6]);  oB[6] = fma2(p2B, v3.x, oB[6]);
        oA[7] = fma2(p2A, v3.y, oA[7]);  oB[7] = fma2(p2B, v3.y, oB[7]);
        jcur = jn;
        k0 = nk0; k1 = nk1; k2 = nk2; k3 = nk3;
    }

    // sparse edge-bias correction: exp(s+f) = exp(s) + exp(s)*expm1(f)
    int base = b * EE;
    #pragma unroll
    for (int qi = 0; qi < 2; qi++) {
        int q = t + qi * 128;
        const unsigned long long* qq = qi ? qB : qA;
        unsigned long long* oo = qi ? oB : oA;
        float* ll = qi ? &lB : &lA;
        int p0 = g_csr_ptr[b * (NN + 1) + q];
        int p1 = g_csr_ptr[b * (NN + 1) + q + 1];
        for (int idx = p0; idx < p1; idx++) {
            int c = g_csr_col[base + idx];
            if (!sm[c]) continue;
            float f = g_ef[base + g_csr_eid[base + idx]];
            const ulonglong2* kpp = reinterpret_cast<const ulonglong2*>(sk + c * DKK);
            ulonglong2 c0v = kpp[0], c1v = kpp[1], c2v = kpp[2], c3v = kpp[3];
            unsigned long long a = 0ull;
            a = fma2(qq[0], c0v.x, a);
            a = fma2(qq[1], c0v.y, a);
            a = fma2(qq[2], c1v.x, a);
            a = fma2(qq[3], c1v.y, a);
            a = fma2(qq[4], c2v.x, a);
            a = fma2(qq[5], c2v.y, a);
            a = fma2(qq[6], c3v.x, a);
            a = fma2(qq[7], c3v.y, a);
            float2 hh = unpack2(a);
            float w = __expf((hh.x + hh.y) * 0.25f) * expm1f(f);
            *ll += w;
            unsigned long long w2 = pack2(w, w);
            const ulonglong2* vp = reinterpret_cast<const ulonglong2*>(sv + c * DKK);
            ulonglong2 v0 = vp[0], v1 = vp[1], v2 = vp[2], v3 = vp[3];
            oo[0] = fma2(w2, v0.x, oo[0]);
            oo[1] = fma2(w2, v0.y, oo[1]);
            oo[2] = fma2(w2, v1.x, oo[2]);
            oo[3] = fma2(w2, v1.y, oo[3]);
            oo[4] = fma2(w2, v2.x, oo[4]);
            oo[5] = fma2(w2, v2.y, oo[5]);
            oo[6] = fma2(w2, v3.x, oo[6]);
            oo[7] = fma2(w2, v3.y, oo[7]);
        }
    }

    float invA = 1.0f / lA, invB = 1.0f / lB;
    float* og = g_o + ((size_t)(b * NN + t)) * DD + h * DKK;
    #pragma unroll
    for (int i = 0; i < 4; i++) {
        float2 e0 = unpack2(oA[2 * i]);
        float2 e1 = unpack2(oA[2 * i + 1]);
        reinterpret_cast<float4*>(og)[i] =
            make_float4(e0.x * invA, e0.y * invA, e1.x * invA, e1.y * invA);
    }
    og = g_o + ((size_t)(b * NN + t + 128)) * DD + h * DKK;
    #pragma unroll
    for (int i = 0; i < 4; i++) {
        float2 e0 = unpack2(oB[2 * i]);
        float2 e1 = unpack2(oB[2 * i + 1]);
        reinterpret_cast<float4*>(og)[i] =
            make_float4(e0.x * invB, e0.y * invB, e1.x * invB, e1.y * invB);
    }
}

// ---------------- kernel 6: residual + layernorm ----------------
__global__ void k_ln(const float* __restrict__ x,
                     const float* __restrict__ lg,
                     const float* __restrict__ lb,
                     float* __restrict__ out) {
    int warp = threadIdx.x >> 5, lane = threadIdx.x & 31;
    int row = blockIdx.x * 8 + warp;
    int c0 = lane * 4;
    float4 o = *reinterpret_cast<const float4*>(g_o + (size_t)row * DD + c0);
    float4 xv = *reinterpret_cast<const float4*>(x + (size_t)row * DD + c0);
    float4 s = make_float4(o.x + xv.x, o.y + xv.y, o.z + xv.z, o.w + xv.w);
    float sum = s.x + s.y + s.z + s.w;
    float sq  = s.x * s.x + s.y * s.y + s.z * s.z + s.w * s.w;
    #pragma unroll
    for (int off = 16; off; off >>= 1) {
        sum += __shfl_xor_sync(0xFFFFFFFFu, sum, off);
        sq  += __shfl_xor_sync(0xFFFFFFFFu, sq, off);
    }
    float mu = sum * (1.0f / DD);
    float var = sq * (1.0f / DD) - mu * mu;
    float rstd = rsqrtf(var + 1e-6f);
    float4 g = *reinterpret_cast<const float4*>(lg + c0);
    float4 be = *reinterpret_cast<const float4*>(lb + c0);
    float4 r;
    r.x = (s.x - mu) * rstd * g.x + be.x;
    r.y = (s.y - mu) * rstd * g.y + be.y;
    r.z = (s.z - mu) * rstd * g.z + be.z;
    r.w = (s.w - mu) * rstd * g.w + be.w;
    *reinterpret_cast<float4*>(out + (size_t)row * DD + c0) = r;
}

// ---------------- launch ----------------
extern "C" void kernel_launch(void* const* d_in, const int* in_sizes, int n_in,
                              void* d_out, int out_size) {
    const float* x    = (const float*)d_in[0];
    const void*  mask = d_in[1];
    const int*   ei   = (const int*)d_in[2];
    const float* ea   = (const float*)d_in[3];
    const float* Wq   = (const float*)d_in[4];
    const float* Wk   = (const float*)d_in[5];
    const float* Wv   = (const float*)d_in[6];
    const float* Wew  = (const float*)d_in[7];
    const float* Web  = (const float*)d_in[8];
    const float* lg   = (const float*)d_in[9];
    const float* lb   = (const float*)d_in[10];
    float* out = (float*)d_out;

    // qkv is launch #4 — the ncu-captured slot.
    k_mask_conv<<<(BB * NN) / 256, 256>>>(mask, Wew, Web);
    k_deg_csr<<<BB, 256>>>(ei);
    k_ef<<<(BB * EE) / 8, 256>>>(ea);

    int smem_qkv = (DIN * XT_STRIDE + DIN * DD) * (int)sizeof(float);
    cudaFuncSetAttribute(k_qkv, cudaFuncAttributeMaxDynamicSharedMemorySize, smem_qkv);
    k_qkv<<<(BB * NN) / 64, 128, smem_qkv>>>(x, Wq, Wk, Wv);

    k_attn<<<BB * HH, 128>>>();
    k_ln<<<(BB * NN) / 8, 256>>>(x, lg, lb, out);
}